// round 13
// baseline (speedup 1.0000x reference)
#include <cuda_runtime.h>
#include <cuda_bf16.h>

#define CCONST 7.1998226
#define THREADS 256
#define MAXB 64

__device__ double g_sum[MAXB];           // zero at load; reset by finalize each run
__device__ unsigned int g_done = 0;      // completion ticket (atomicInc wraps)

__global__ __launch_bounds__(THREADS, 4)
void coulomb_span(const float* __restrict__ dij,
                  const float* __restrict__ q,
                  float* __restrict__ out,
                  int N, int B, unsigned int totalBlocks) {
    const int b   = blockIdx.y;
    const int bid = blockIdx.x;
    const int bpb = gridDim.x;
    const int tid = threadIdx.x;
    const int n4    = N >> 2;
    const int half4 = N >> 3;

    const float* qb = q + (size_t)b * N;
    const float4* q4 = (const float4*)qb;

    // split column ownership: cols [4t,4t+4) and [N/2+4t, N/2+4t+4)
    const float4 qa = __ldg(q4 + tid);
    const float4 qc = __ldg(q4 + half4 + tid);

    // exact even row span: each block gets floor-partitioned contiguous rows
    int r    = (int)(((long long)bid * N) / bpb);
    const int rEnd = (int)(((long long)(bid + 1) * N) / bpb);

    double acc = 0.0;

    // main: 4-row groups, 8 fully-coalesced LDG.128 front-batched
    for (; r + 4 <= rEnd; r += 4) {
        const float4* base4 = (const float4*)(dij + ((size_t)b * N + r) * (size_t)N);
        const float4* p0 = base4;
        const float4* p1 = base4 + (size_t)n4;
        const float4* p2 = base4 + (size_t)2 * n4;
        const float4* p3 = base4 + (size_t)3 * n4;

        float4 da0 = __ldcs(p0 + tid);
        float4 dc0 = __ldcs(p0 + half4 + tid);
        float4 da1 = __ldcs(p1 + tid);
        float4 dc1 = __ldcs(p1 + half4 + tid);
        float4 da2 = __ldcs(p2 + tid);
        float4 dc2 = __ldcs(p2 + half4 + tid);
        float4 da3 = __ldcs(p3 + tid);
        float4 dc3 = __ldcs(p3 + half4 + tid);

        const float qi0 = __ldg(qb + r);
        const float qi1 = __ldg(qb + r + 1);
        const float qi2 = __ldg(qb + r + 2);
        const float qi3 = __ldg(qb + r + 3);

        float l0 = __fdividef(qa.x, da0.x) + __fdividef(qa.y, da0.y)
                 + __fdividef(qa.z, da0.z) + __fdividef(qa.w, da0.w)
                 + __fdividef(qc.x, dc0.x) + __fdividef(qc.y, dc0.y)
                 + __fdividef(qc.z, dc0.z) + __fdividef(qc.w, dc0.w);

        float l1 = __fdividef(qa.x, da1.x) + __fdividef(qa.y, da1.y)
                 + __fdividef(qa.z, da1.z) + __fdividef(qa.w, da1.w)
                 + __fdividef(qc.x, dc1.x) + __fdividef(qc.y, dc1.y)
                 + __fdividef(qc.z, dc1.z) + __fdividef(qc.w, dc1.w);

        float l2 = __fdividef(qa.x, da2.x) + __fdividef(qa.y, da2.y)
                 + __fdividef(qa.z, da2.z) + __fdividef(qa.w, da2.w)
                 + __fdividef(qc.x, dc2.x) + __fdividef(qc.y, dc2.y)
                 + __fdividef(qc.z, dc2.z) + __fdividef(qc.w, dc2.w);

        float l3 = __fdividef(qa.x, da3.x) + __fdividef(qa.y, da3.y)
                 + __fdividef(qa.z, da3.z) + __fdividef(qa.w, da3.w)
                 + __fdividef(qc.x, dc3.x) + __fdividef(qc.y, dc3.y)
                 + __fdividef(qc.z, dc3.z) + __fdividef(qc.w, dc3.w);

        float g0 = fmaf(qi0, l0, qi1 * l1);
        float g1 = fmaf(qi2, l2, qi3 * l3);
        acc += (double)g0 + (double)g1;   // promote per 4-row group
    }

    // remainder rows (<= 3)
    for (; r < rEnd; r++) {
        const float4* p = (const float4*)(dij + ((size_t)b * N + r) * (size_t)N);
        float4 da = __ldcs(p + tid);
        float4 dc = __ldcs(p + half4 + tid);
        float l = __fdividef(qa.x, da.x) + __fdividef(qa.y, da.y)
                + __fdividef(qa.z, da.z) + __fdividef(qa.w, da.w)
                + __fdividef(qc.x, dc.x) + __fdividef(qc.y, dc.y)
                + __fdividef(qc.z, dc.z) + __fdividef(qc.w, dc.w);
        acc += (double)__ldg(qb + r) * (double)l;
    }

    // block reduce (fp64)
    #pragma unroll
    for (int off = 16; off; off >>= 1)
        acc += __shfl_down_sync(0xffffffffu, acc, off);

    __shared__ double sm[THREADS / 32];
    __shared__ bool is_last;
    if ((tid & 31) == 0) sm[tid >> 5] = acc;
    __syncthreads();

    if (tid < 32) {
        double v = (tid < THREADS / 32) ? sm[tid] : 0.0;
        #pragma unroll
        for (int off = 4; off; off >>= 1)
            v += __shfl_down_sync(0xffffffffu, v, off);
        if (tid == 0) {
            atomicAdd(&g_sum[b], v);
            __threadfence();
            unsigned int ticket = atomicInc(&g_done, totalBlocks - 1);
            is_last = (ticket == totalBlocks - 1);
        }
    }
    __syncthreads();

    if (is_last && tid < B) {
        double total = atomicAdd(&g_sum[tid], 0.0);   // coherent read
        out[tid] = (float)(CCONST * total);
        g_sum[tid] = 0.0;                             // reset for next replay
    }
}

extern "C" void kernel_launch(void* const* d_in, const int* in_sizes, int n_in,
                              void* d_out, int out_size) {
    // Identify inputs by element count: largest = d_ij [B,N,N]; q = [B,N].
    int di = 0;
    for (int i = 1; i < n_in; i++)
        if (in_sizes[i] > in_sizes[di]) di = i;
    const float* dij = (const float*)d_in[di];

    const long long B = (out_size > 0) ? out_size : 16;
    int qi = (di == 0 && n_in > 1) ? 1 : 0;
    for (int i = 0; i < n_in; i++) {
        if (i == di) continue;
        long long nq = in_sizes[i];
        long long Nc = nq / B;
        if (Nc > 0 && B * Nc * Nc == (long long)in_sizes[di]) { qi = i; break; }
    }
    const float* q = (const float*)d_in[qi];

    const int N = (int)((long long)in_sizes[qi] / B);   // 2048

    int sm_count = 148;
    cudaDeviceGetAttribute(&sm_count, cudaDevAttrMultiProcessorCount, 0);

    int bpb = (sm_count * 4) / (int)B;                  // 152*4/16 = 38
    if (bpb < 1) bpb = 1;
    if (bpb > N) bpb = N;

    const unsigned int totalBlocks = (unsigned int)(bpb * B);
    dim3 grid(bpb, (unsigned)B);
    coulomb_span<<<grid, THREADS>>>(dij, q, (float*)d_out, N, (int)B, totalBlocks);
}